// round 1
// baseline (speedup 1.0000x reference)
#include <cuda_runtime.h>
#include <cstdint>

#define NPTS  32768
#define NB    8
#define PPC   4096     // points per cloud
#define DIN   64
#define MCTR  8192
#define KNB   32
#define R2    0.04f
#define K1    67       // DIN + 3
#define STRIDE 132     // padded row stride for transposed activation tiles

__device__ int      g_nbr[MCTR * KNB];
__device__ unsigned g_valid[MCTR];

// ---------------------------------------------------------------------------
// KNN kernel: one warp per center. Distributed top-32 (one key per lane).
// key = orderable(d2)<<32 | global_point_index  -> replicates lax.top_k ties.
// ---------------------------------------------------------------------------
__device__ __forceinline__ unsigned long long warp_max_ull(unsigned long long v) {
#pragma unroll
    for (int o = 16; o; o >>= 1) {
        unsigned long long t = __shfl_xor_sync(0xffffffffu, v, o);
        v = t > v ? t : v;
    }
    return v;
}

__global__ void knn_kernel(const float* __restrict__ pos,
                           const int* __restrict__ batch,
                           const int* __restrict__ idx,
                           float* __restrict__ posout,
                           float* __restrict__ batchout,
                           int writeAux)
{
    int warp = (blockIdx.x * blockDim.x + threadIdx.x) >> 5;
    int lane = threadIdx.x & 31;
    if (warp >= MCTR) return;

    int ci = idx[warp];
    int b  = batch[ci];
    int cb = b * PPC;

    float c0 = pos[ci * 3 + 0], c1 = pos[ci * 3 + 1], c2 = pos[ci * 3 + 2];
    float cs = c0 * c0 + c1 * c1 + c2 * c2;

    unsigned long long kept   = 0xffffffffffffffffull;
    unsigned long long curmax = 0xffffffffffffffffull;

    for (int base = 0; base < PPC; base += 32) {
        int j = cb + base + lane;
        float p0 = pos[j * 3 + 0], p1 = pos[j * 3 + 1], p2 = pos[j * 3 + 2];
        float ps = p0 * p0 + p1 * p1 + p2 * p2;
        float dt = c0 * p0 + c1 * p1 + c2 * p2;
        float d2 = (cs + ps) - 2.0f * dt;   // same expansion as reference

        unsigned u   = __float_as_uint(d2);
        unsigned ord = (u & 0x80000000u) ? ~u : (u | 0x80000000u);
        unsigned long long ck = ((unsigned long long)ord << 32) | (unsigned)j;

        unsigned mask = __ballot_sync(0xffffffffu, ck < curmax);
        if (mask) {
            while (mask) {
                int s = __ffs(mask) - 1; mask &= mask - 1;
                unsigned long long cand = __shfl_sync(0xffffffffu, ck, s);
                unsigned long long mx = warp_max_ull(kept);
                if (cand < mx) {
                    unsigned who = __ballot_sync(0xffffffffu, kept == mx);
                    if (lane == (__ffs(who) - 1)) kept = cand;
                }
            }
            curmax = warp_max_ull(kept);
        }
    }

    unsigned nb   = (unsigned)(kept & 0xffffffffu);
    unsigned ordb = (unsigned)(kept >> 32);
    unsigned ub   = (ordb & 0x80000000u) ? (ordb ^ 0x80000000u) : ~ordb;
    float d2v = __uint_as_float(ub);

    g_nbr[warp * KNB + lane] = (int)nb;
    unsigned vm = __ballot_sync(0xffffffffu, d2v <= R2);
    if (lane == 0) g_valid[warp] = vm;

    if (writeAux) {
        if (lane < 3)   posout[warp * 3 + lane] = pos[ci * 3 + lane];
        if (lane == 3)  batchout[warp] = (float)b;
    }
}

// ---------------------------------------------------------------------------
// Packed f32x2 helpers (Blackwell)
// ---------------------------------------------------------------------------
__device__ __forceinline__ unsigned long long pack2(float lo, float hi) {
    unsigned long long r;
    asm("mov.b64 %0, {%1, %2};" : "=l"(r) : "f"(lo), "f"(hi));
    return r;
}
__device__ __forceinline__ void fma2(unsigned long long& d, unsigned long long a, unsigned long long b) {
    asm("fma.rn.f32x2 %0, %1, %2, %0;" : "+l"(d) : "l"(a), "l"(b));
}
__device__ __forceinline__ void unpack2(unsigned long long v, float& lo, float& hi) {
    asm("mov.b64 {%0, %1}, %2;" : "=f"(lo), "=f"(hi) : "l"(v));
}

// ---------------------------------------------------------------------------
// Shared-memory GEMM core: C[128 x 128] += A_T[k][row] * B[k][col]
// A_T in smem (stride STRIDE), W streamed global -> Bt smem tile [16][128].
// Each thread: 8 rows x 8 cols, rows packed in f32x2 pairs.
// ---------------------------------------------------------------------------
__device__ __forceinline__ void gemm128(const float* __restrict__ AT, int ktiles, int kreal,
                                        const float* __restrict__ Wsrc, int wStride, int colOff,
                                        float* Bt, unsigned long long acc[4][8], int tid)
{
    int tr = tid >> 4, tc = tid & 15;
    int r0 = tr * 8, c0 = tc * 8;

    for (int kt = 0; kt < ktiles; kt++) {
        __syncthreads();
        int k0 = kt * 16;
        for (int t = tid; t < 16 * 32; t += 256) {    // 16 rows x 32 float4
            int kk = t >> 5;
            int c4 = (t & 31) * 4;
            int kg = k0 + kk;
            float4 v = make_float4(0.f, 0.f, 0.f, 0.f);
            if (kg < kreal) v = *(const float4*)(Wsrc + kg * wStride + colOff + c4);
            *(float4*)(Bt + kk * 128 + c4) = v;
        }
        __syncthreads();
#pragma unroll
        for (int kk = 0; kk < 16; kk++) {
            const float* arow = AT + (k0 + kk) * STRIDE + r0;
            ulonglong2 a01 = *(const ulonglong2*)(arow);
            ulonglong2 a23 = *(const ulonglong2*)(arow + 4);
            unsigned long long ap[4] = {a01.x, a01.y, a23.x, a23.y};
            float4 bA = *(const float4*)(Bt + kk * 128 + c0);
            float4 bB = *(const float4*)(Bt + kk * 128 + c0 + 4);
            float bs[8] = {bA.x, bA.y, bA.z, bA.w, bB.x, bB.y, bB.z, bB.w};
#pragma unroll
            for (int i = 0; i < 8; i++) {
                unsigned long long bb = pack2(bs[i], bs[i]);
#pragma unroll
                for (int p = 0; p < 4; p++) fma2(acc[p][i], ap[p], bb);
            }
        }
    }
}

__device__ __forceinline__ void zero_acc(unsigned long long acc[4][8]) {
#pragma unroll
    for (int p = 0; p < 4; p++)
#pragma unroll
        for (int i = 0; i < 8; i++) acc[p][i] = 0ull;
}

__device__ __forceinline__ void epilogue_store(unsigned long long acc[4][8],
                                               const float* __restrict__ bias,
                                               float* CT, int tid)
{
    int tr = tid >> 4, tc = tid & 15;
    int r0 = tr * 8, c0 = tc * 8;
#pragma unroll
    for (int i = 0; i < 8; i++) {
        int col = c0 + i;
        float bv = bias[col];
        float v[8];
#pragma unroll
        for (int p = 0; p < 4; p++) unpack2(acc[p][i], v[2 * p], v[2 * p + 1]);
#pragma unroll
        for (int r = 0; r < 8; r++) v[r] = fmaxf(v[r] + bv, 0.0f);
        *(float4*)(CT + col * STRIDE + r0)     = make_float4(v[0], v[1], v[2], v[3]);
        *(float4*)(CT + col * STRIDE + r0 + 4) = make_float4(v[4], v[5], v[6], v[7]);
    }
}

__device__ __forceinline__ void epilogue_max(unsigned long long acc[4][8],
                                             const float* __restrict__ bias, int colBase,
                                             float* out4, const unsigned* validm, int tid)
{
    int tr = tid >> 4, tc = tid & 15;
    int r0 = tr * 8, c0 = tc * 8;
    int g = r0 >> 5;                     // all 8 rows of this thread share one group
    unsigned vm = validm[g] >> (r0 & 31);
#pragma unroll
    for (int i = 0; i < 8; i++) {
        int col = colBase + c0 + i;
        float bv = bias[col];
        float mx = 0.0f;                 // safe: >=1 valid nbr, relu >= 0
#pragma unroll
        for (int p = 0; p < 4; p++) {
            float lo, hi; unpack2(acc[p][i], lo, hi);
            if ((vm >> (2 * p)) & 1)     mx = fmaxf(mx, fmaxf(lo + bv, 0.0f));
            if ((vm >> (2 * p + 1)) & 1) mx = fmaxf(mx, fmaxf(hi + bv, 0.0f));
        }
        atomicMax((int*)(out4 + g * 256 + col), __float_as_int(mx));
    }
}

// ---------------------------------------------------------------------------
// MLP kernel: 4 centers (128 edge rows) per block, fused 3-layer MLP + max.
// ---------------------------------------------------------------------------
#define SMEM_FLOATS (80 * STRIDE + 2 * 128 * STRIDE + 16 * 128 + 1024 + 128 + 4 + 12)
#define SMEM_BYTES  (SMEM_FLOATS * 4)

__global__ void __launch_bounds__(256, 1)
mlp_kernel(const float* __restrict__ x, const float* __restrict__ pos,
           const int* __restrict__ idx,
           const float* __restrict__ W1, const float* __restrict__ b1,
           const float* __restrict__ W2, const float* __restrict__ b2,
           const float* __restrict__ W3, const float* __restrict__ b3,
           float* __restrict__ out)
{
    extern __shared__ float sm[];
    float*    featT  = sm;                          // [80][STRIDE]
    float*    h1T    = featT + 80 * STRIDE;         // [128][STRIDE]
    float*    h2T    = h1T + 128 * STRIDE;          // [128][STRIDE]
    float*    Bt     = h2T + 128 * STRIDE;          // [16][128]
    float*    out4   = Bt + 16 * 128;               // [4][256]
    int*      nbrs   = (int*)(out4 + 1024);         // [128]
    unsigned* validm = (unsigned*)(nbrs + 128);     // [4]
    float*    cpos   = (float*)(validm + 4);        // [4][3]

    int tid = threadIdx.x;
    int m0  = blockIdx.x * 4;

    if (tid < 128) nbrs[tid] = g_nbr[m0 * KNB + tid];
    if (tid < 4)   validm[tid] = g_valid[m0 + tid];
    if (tid >= 128 && tid < 140) {
        int t = tid - 128;
        cpos[t] = pos[idx[m0 + t / 3] * 3 + (t % 3)];
    }
    for (int t = tid; t < 1024; t += 256) out4[t] = 0.0f;
    __syncthreads();

    // Build featT = [ x[nbr] (64) | rel (3) | zero-pad (13) ] transposed.
    {
        int row  = tid >> 1;
        int half = tid & 1;
        int nb   = nbrs[row];
        const float* xr = x + nb * DIN + half * 32;
#pragma unroll
        for (int i = 0; i < 8; i++) {
            float4 v = *(const float4*)(xr + i * 4);
            int k = half * 32 + i * 4;
            featT[(k + 0) * STRIDE + row] = v.x;
            featT[(k + 1) * STRIDE + row] = v.y;
            featT[(k + 2) * STRIDE + row] = v.z;
            featT[(k + 3) * STRIDE + row] = v.w;
        }
        if (half) {
            int c = row >> 5;
            featT[64 * STRIDE + row] = pos[nb * 3 + 0] - cpos[c * 3 + 0];
            featT[65 * STRIDE + row] = pos[nb * 3 + 1] - cpos[c * 3 + 1];
            featT[66 * STRIDE + row] = pos[nb * 3 + 2] - cpos[c * 3 + 2];
        }
        for (int t = tid; t < 13 * 128; t += 256)
            featT[(67 + (t >> 7)) * STRIDE + (t & 127)] = 0.0f;
    }
    // (gemm128's leading __syncthreads orders featT writes before reads)

    unsigned long long acc[4][8];

    // Layer 1: [128 x 67] @ [67 x 128]
    zero_acc(acc);
    gemm128(featT, 5, K1, W1, 128, 0, Bt, acc, tid);
    epilogue_store(acc, b1, h1T, tid);

    // Layer 2: [128 x 128] @ [128 x 128]
    zero_acc(acc);
    gemm128(h1T, 8, 128, W2, 128, 0, Bt, acc, tid);
    epilogue_store(acc, b2, h2T, tid);

    // Layer 3: [128 x 128] @ [128 x 256] in two column halves + masked max
    for (int h = 0; h < 2; h++) {
        zero_acc(acc);
        gemm128(h2T, 8, 128, W3, 256, h * 128, Bt, acc, tid);
        epilogue_max(acc, b3, h * 128, out4, validm, tid);
    }

    __syncthreads();
    for (int t = tid; t < 1024; t += 256)
        out[(m0 + (t >> 8)) * 256 + (t & 255)] = out4[t];
}

// ---------------------------------------------------------------------------
extern "C" void kernel_launch(void* const* d_in, const int* in_sizes, int n_in,
                              void* d_out, int out_size)
{
    const float* x     = (const float*)d_in[0];
    const float* pos   = (const float*)d_in[1];
    const int*   batch = (const int*)d_in[2];
    const int*   idx   = (const int*)d_in[3];
    const float* W1 = (const float*)d_in[4];
    const float* b1 = (const float*)d_in[5];
    const float* W2 = (const float*)d_in[6];
    const float* b2 = (const float*)d_in[7];
    const float* W3 = (const float*)d_in[8];
    const float* b3 = (const float*)d_in[9];

    float* out = (float*)d_out;
    int writeAux = (out_size >= MCTR * 256 + MCTR * 3 + MCTR) ? 1 : 0;
    float* posout   = out + MCTR * 256;
    float* batchout = posout + MCTR * 3;

    knn_kernel<<<MCTR / 8, 256>>>(pos, batch, idx, posout, batchout, writeAux);

    cudaFuncSetAttribute(mlp_kernel, cudaFuncAttributeMaxDynamicSharedMemorySize, SMEM_BYTES);
    mlp_kernel<<<MCTR / 4, 256, SMEM_BYTES>>>(x, pos, idx, W1, b1, W2, b2, W3, b3, out);
}

// round 4
// speedup vs baseline: 2.0038x; 2.0038x over previous
#include <cuda_runtime.h>
#include <cuda_bf16.h>
#include <cstdint>

#define NPTS  32768
#define NB    8
#define PPC   4096
#define DIN   64
#define MCTR  8192
#define KNB   32
#define R2    0.04f

__device__ int      g_nbr[MCTR * KNB];
__device__ unsigned g_valid[MCTR];
// 4 units x (32KB hi plane + 32KB lo plane), pre-swizzled B[n][k] images
__device__ __align__(16) unsigned char g_wimg[4 * 65536];

// ---------------------------------------------------------------------------
// helpers
// ---------------------------------------------------------------------------
__device__ __forceinline__ uint32_t smem_u32(const void* p) {
    uint32_t a;
    asm("{ .reg .u64 t; cvta.to.shared.u64 t, %1; cvt.u32.u64 %0, t; }" : "=r"(a) : "l"(p));
    return a;
}

// swizzled byte offset inside a [128 rows][128 bf16] plane (256B rows,
// 16B-unit XOR by row&7 -> conflict-free ldmatrix)
__device__ __forceinline__ uint32_t poff(uint32_t r, uint32_t c) {
    return r * 256u + ((c * 2u) ^ ((r & 7u) << 4));
}

__device__ __forceinline__ void split2(float a, float b, uint32_t& hi, uint32_t& lo) {
    __nv_bfloat16 ha = __float2bfloat16(a), hb = __float2bfloat16(b);
    float ra = a - __bfloat162float(ha), rb = b - __bfloat162float(hb);
    __nv_bfloat162 H; H.x = ha; H.y = hb;
    __nv_bfloat162 L; L.x = __float2bfloat16(ra); L.y = __float2bfloat16(rb);
    hi = *(uint32_t*)&H;
    lo = *(uint32_t*)&L;
}

#define LDSM4(a, r0, r1, r2, r3) \
    asm volatile("ldmatrix.sync.aligned.m8n8.x4.shared.b16 {%0,%1,%2,%3}, [%4];" \
        : "=r"(r0), "=r"(r1), "=r"(r2), "=r"(r3) : "r"(a))

__device__ __forceinline__ void mma16816(float* c, uint32_t a0, uint32_t a1, uint32_t a2,
                                         uint32_t a3, uint32_t b0, uint32_t b1) {
    asm volatile("mma.sync.aligned.m16n8k16.row.col.f32.bf16.bf16.f32 "
        "{%0,%1,%2,%3}, {%4,%5,%6,%7}, {%8,%9}, {%0,%1,%2,%3};"
        : "+f"(c[0]), "+f"(c[1]), "+f"(c[2]), "+f"(c[3])
        : "r"(a0), "r"(a1), "r"(a2), "r"(a3), "r"(b0), "r"(b1));
}

#define CP_ASYNC16(dst, src) \
    asm volatile("cp.async.cg.shared.global [%0], [%1], 16;" :: "r"(dst), "l"(src))
#define CP_COMMIT  asm volatile("cp.async.commit_group;" ::: "memory")
#define CP_WAIT0   asm volatile("cp.async.wait_group 0;" ::: "memory")

// ---------------------------------------------------------------------------
// Weight prep: split fp32 W -> bf16 hi/lo, write pre-swizzled B[n][k] image.
// unit 0: W1 (K padded 67->128), 1: W2, 2: W3[:, :128], 3: W3[:, 128:]
// ---------------------------------------------------------------------------
__global__ void prep_kernel(const float* __restrict__ W1, const float* __restrict__ W2,
                            const float* __restrict__ W3) {
    int t = blockIdx.x * blockDim.x + threadIdx.x;   // 65536
    int u = t >> 14, n = (t >> 7) & 127, k = t & 127;
    float w = 0.0f;
    if (u == 0)      { if (k < 67) w = W1[k * 128 + n]; }
    else if (u == 1) w = W2[k * 128 + n];
    else if (u == 2) w = W3[k * 256 + n];
    else             w = W3[k * 256 + 128 + n];
    __nv_bfloat16 h = __float2bfloat16(w);
    __nv_bfloat16 l = __float2bfloat16(w - __bfloat162float(h));
    uint32_t off = poff(n, k);
    unsigned char* base = g_wimg + u * 65536;
    *(__nv_bfloat16*)(base + off)         = h;
    *(__nv_bfloat16*)(base + 32768 + off) = l;
}

// ---------------------------------------------------------------------------
// KNN kernel (verified rel_err 0.0 in R1)
// ---------------------------------------------------------------------------
__device__ __forceinline__ unsigned long long warp_max_ull(unsigned long long v) {
#pragma unroll
    for (int o = 16; o; o >>= 1) {
        unsigned long long t = __shfl_xor_sync(0xffffffffu, v, o);
        v = t > v ? t : v;
    }
    return v;
}

__global__ void knn_kernel(const float* __restrict__ pos,
                           const int* __restrict__ batch,
                           const int* __restrict__ idx,
                           float* __restrict__ posout,
                           float* __restrict__ batchout,
                           int writeAux)
{
    int warp = (blockIdx.x * blockDim.x + threadIdx.x) >> 5;
    int lane = threadIdx.x & 31;
    if (warp >= MCTR) return;

    int ci = idx[warp];
    int b  = batch[ci];
    int cb = b * PPC;

    float c0 = pos[ci * 3 + 0], c1 = pos[ci * 3 + 1], c2 = pos[ci * 3 + 2];
    float cs = c0 * c0 + c1 * c1 + c2 * c2;

    unsigned long long kept   = 0xffffffffffffffffull;
    unsigned long long curmax = 0xffffffffffffffffull;

    for (int base = 0; base < PPC; base += 32) {
        int j = cb + base + lane;
        float p0 = pos[j * 3 + 0], p1 = pos[j * 3 + 1], p2 = pos[j * 3 + 2];
        float ps = p0 * p0 + p1 * p1 + p2 * p2;
        float dt = c0 * p0 + c1 * p1 + c2 * p2;
        float d2 = (cs + ps) - 2.0f * dt;

        unsigned u   = __float_as_uint(d2);
        unsigned ord = (u & 0x80000000u) ? ~u : (u | 0x80000000u);
        unsigned long long ck = ((unsigned long long)ord << 32) | (unsigned)j;

        unsigned mask = __ballot_sync(0xffffffffu, ck < curmax);
        if (mask) {
            while (mask) {
                int s = __ffs(mask) - 1; mask &= mask - 1;
                unsigned long long cand = __shfl_sync(0xffffffffu, ck, s);
                unsigned long long mx = warp_max_ull(kept);
                if (cand < mx) {
                    unsigned who = __ballot_sync(0xffffffffu, kept == mx);
                    if (lane == (__ffs(who) - 1)) kept = cand;
                }
            }
            curmax = warp_max_ull(kept);
        }
    }

    unsigned nb   = (unsigned)(kept & 0xffffffffu);
    unsigned ordb = (unsigned)(kept >> 32);
    unsigned ub   = (ordb & 0x80000000u) ? (ordb ^ 0x80000000u) : ~ordb;
    float d2v = __uint_as_float(ub);

    g_nbr[warp * KNB + lane] = (int)nb;
    unsigned vm = __ballot_sync(0xffffffffu, d2v <= R2);
    if (lane == 0) g_valid[warp] = vm;

    if (writeAux) {
        if (lane < 3)   posout[warp * 3 + lane] = pos[ci * 3 + lane];
        if (lane == 3)  batchout[warp] = (float)b;
    }
}

// ---------------------------------------------------------------------------
// MLP kernel: mma.sync bf16 3-term compensated, fused 3 layers + masked max.
// 8 warps; warp w owns M-rows [16w, 16w+16). 4 centers per block.
// ---------------------------------------------------------------------------
#define OFF_A   8192u
#define OFF_B0  73728u
#define OFF_B1  139264u
#define SMEM_TOTAL 204800

__global__ void __launch_bounds__(256, 1)
mlp_kernel(const float* __restrict__ x, const float* __restrict__ pos,
           const int* __restrict__ idx,
           const float* __restrict__ b1, const float* __restrict__ b2,
           const float* __restrict__ b3, float* __restrict__ out)
{
    extern __shared__ char smc[];
    float* bias_s = (float*)smc;           // 512 floats
    float* wmax   = (float*)(smc + 2048);  // 8*128 floats
    uint32_t sb = smem_u32(smc);

    int tid = threadIdx.x, wid = tid >> 5, lane = tid & 31;
    int m0 = blockIdx.x * 4;

    // ---------------- phase 0: feature tile + bias + stage W(unit0) --------
    if (tid < 128) {
        int row = tid;
        int nb  = g_nbr[m0 * KNB + row];
        int ci  = idx[m0 + (row >> 5)];
        const float4* xr = (const float4*)(x + nb * DIN);
#pragma unroll
        for (int i = 0; i < 16; i++) {
            float4 v = __ldg(xr + i);
            uint32_t h0, l0, h1, l1;
            split2(v.x, v.y, h0, l0);
            split2(v.z, v.w, h1, l1);
            uint32_t o0 = poff(row, 4 * i), o1 = poff(row, 4 * i + 2);
            *(uint32_t*)(smc + OFF_A + o0)         = h0;
            *(uint32_t*)(smc + OFF_A + 32768 + o0) = l0;
            *(uint32_t*)(smc + OFF_A + o1)         = h1;
            *(uint32_t*)(smc + OFF_A + 32768 + o1) = l1;
        }
        float r0v = pos[nb * 3 + 0] - pos[ci * 3 + 0];
        float r1v = pos[nb * 3 + 1] - pos[ci * 3 + 1];
        float r2v = pos[nb * 3 + 2] - pos[ci * 3 + 2];
        uint32_t h, l;
        split2(r0v, r1v, h, l);
        { uint32_t o = poff(row, 64);
          *(uint32_t*)(smc + OFF_A + o) = h; *(uint32_t*)(smc + OFF_A + 32768 + o) = l; }
        split2(r2v, 0.0f, h, l);
        { uint32_t o = poff(row, 66);
          *(uint32_t*)(smc + OFF_A + o) = h; *(uint32_t*)(smc + OFF_A + 32768 + o) = l; }
#pragma unroll
        for (int c = 68; c < 128; c += 2) {
            uint32_t o = poff(row, c);
            *(uint32_t*)(smc + OFF_A + o) = 0u; *(uint32_t*)(smc + OFF_A + 32768 + o) = 0u;
        }
    } else {
        int j = tid - 128;
        if (j < 32)       ((float4*)bias_s)[j]      = ((const float4*)b1)[j];
        else if (j < 64)  ((float4*)bias_s)[j]      = ((const float4*)b2)[j - 32];
        else              ((float4*)bias_s)[j]      = ((const float4*)b3)[j - 64];
        int ct = j;
        const char* src = (const char*)g_wimg;
        for (int i = ct; i < 4096; i += 128)
            CP_ASYNC16(sb + OFF_B0 + i * 16, src + (size_t)i * 16);
    }
    CP_COMMIT;

    // per-warp/lane ldmatrix address constants
    int l7 = lane & 7, lh = (lane >> 3) & 1, lq = lane >> 4;
    int r0w = wid * 16;
    uint32_t arow   = (uint32_t)(r0w + l7 + lh * 8);
    uint32_t a_base = sb + OFF_A + arow * 256u;
    uint32_t arx    = (arow & 7u) << 4;
    uint32_t alk    = (uint32_t)lq * 16u;
    uint32_t browo  = (uint32_t)(l7 + lq * 8) * 256u;
    uint32_t brx    = ((uint32_t)l7 & 7u) << 4;
    uint32_t blk    = (uint32_t)lh * 16u;

    int gid = lane >> 2, tig = lane & 3;

    for (int u = 0; u < 4; u++) {
        CP_WAIT0;
        __syncthreads();   // A tile + B(u) buffer ready for everyone

        // prefetch next unit's weights into the other buffer
        if (u < 3) {
            const char* src = (const char*)g_wimg + (size_t)(u + 1) * 65536;
            uint32_t dst = sb + (((u + 1) & 1) ? OFF_B1 : OFF_B0);
            for (int i = tid; i < 4096; i += 256)
                CP_ASYNC16(dst + i * 16, src + (size_t)i * 16);
            CP_COMMIT;
        }

        uint32_t bufb = sb + ((u & 1) ? OFF_B1 : OFF_B0);
        float acc[64];
#pragma unroll
        for (int i = 0; i < 64; i++) acc[i] = 0.0f;

#pragma unroll
        for (int kt = 0; kt < 8; kt++) {
            uint32_t k2 = (uint32_t)kt * 32u;
            uint32_t aa = a_base + ((k2 + alk) ^ arx);
            uint32_t ah0, ah1, ah2, ah3, al0, al1, al2, al3;
            LDSM4(aa,         ah0, ah1, ah2, ah3);
            LDSM4(aa + 32768, al0, al1, al2, al3);
#pragma unroll
            for (int np = 0; np < 8; np++) {
                uint32_t ba = bufb + (uint32_t)np * 4096u + browo + ((k2 + blk) ^ brx);
                uint32_t bh0, bh1, bh2, bh3, bl0, bl1, bl2, bl3;
                LDSM4(ba,         bh0, bh1, bh2, bh3);
                LDSM4(ba + 32768, bl0, bl1, bl2, bl3);
                mma16816(&acc[(2 * np)     * 4], ah0, ah1, ah2, ah3, bh0, bh1);
                mma16816(&acc[(2 * np + 1) * 4], ah0, ah1, ah2, ah3, bh2, bh3);
                mma16816(&acc[(2 * np)     * 4], ah0, ah1, ah2, ah3, bl0, bl1);
                mma16816(&acc[(2 * np + 1) * 4], ah0, ah1, ah2, ah3, bl2, bl3);
                mma16816(&acc[(2 * np)     * 4], al0, al1, al2, al3, bh0, bh1);
                mma16816(&acc[(2 * np + 1) * 4], al0, al1, al2, al3, bh2, bh3);
            }
        }

        __syncthreads();   // all mma reads of A done before epilogue rewrites A

        if (u < 2) {
            int bo = u * 128;
            int rowA = r0w + gid, rowB = rowA + 8;
#pragma unroll
            for (int np = 0; np < 8; np++)
#pragma unroll
                for (int t = 0; t < 2; t++) {
                    int col = np * 16 + t * 8 + 2 * tig;
                    float* c = &acc[(2 * np + t) * 4];
                    float b0v = bias_s[bo + col], b1v = bias_s[bo + col + 1];
                    float v0 = fmaxf(c[0] + b0v, 0.0f), v1 = fmaxf(c[1] + b1v, 0.0f);
                    float v2 = fmaxf(c[2] + b0v, 0.0f), v3 = fmaxf(c[3] + b1v, 0.0f);
                    uint32_t h, l;
                    split2(v0, v1, h, l);
                    { uint32_t o = poff((uint32_t)rowA, (uint32_t)col);
                      *(uint32_t*)(smc + OFF_A + o) = h;
                      *(uint32_t*)(smc + OFF_A + 32768 + o) = l; }
                    split2(v2, v3, h, l);
                    { uint32_t o = poff((uint32_t)rowB, (uint32_t)col);
                      *(uint32_t*)(smc + OFF_A + o) = h;
                      *(uint32_t*)(smc + OFF_A + 32768 + o) = l; }
                }
        } else {
            int half = u - 2;
            int g = wid >> 1;
            unsigned vm = g_valid[m0 + g];
            int bitbase = (wid & 1) * 16;
            bool okA = (vm >> (bitbase + gid)) & 1u;
            bool okB = (vm >> (bitbase + gid + 8)) & 1u;
#pragma unroll
            for (int np = 0; np < 8; np++)
#pragma unroll
                for (int t = 0; t < 2; t++) {
                    int col = np * 16 + t * 8 + 2 * tig;
                    float* c = &acc[(2 * np + t) * 4];
                    float b0v = bias_s[256 + half * 128 + col];
                    float b1v = bias_s[256 + half * 128 + col + 1];
                    float m0v = fmaxf(okA ? fmaxf(c[0] + b0v, 0.0f) : 0.0f,
                                      okB ? fmaxf(c[2] + b0v, 0.0f) : 0.0f);
                    float m1v = fmaxf(okA ? fmaxf(c[1] + b1v, 0.0f) : 0.0f,
                                      okB ? fmaxf(c[3] + b1v, 0.0f) : 0.0f);
#pragma unroll
                    for (int o = 4; o <= 16; o <<= 1) {
                        m0v = fmaxf(m0v, __shfl_xor_sync(0xffffffffu, m0v, o));
                        m1v = fmaxf(m1v, __shfl_xor_sync(0xffffffffu, m1v, o));
                    }
                    if (lane < 4) {
                        wmax[wid * 128 + col]     = m0v;
                        wmax[wid * 128 + col + 1] = m1v;
                    }
                }
            __syncthreads();
            for (int e = tid; e < 512; e += 256) {
                int gg = e >> 7, col = e & 127;
                float v = fmaxf(wmax[(gg * 2) * 128 + col], wmax[(gg * 2 + 1) * 128 + col]);
                out[(size_t)(m0 + gg) * 256 + half * 128 + col] = v;
            }
        }
    }
}

// ---------------------------------------------------------------------------
extern "C" void kernel_launch(void* const* d_in, const int* in_sizes, int n_in,
                              void* d_out, int out_size)
{
    const float* x     = (const float*)d_in[0];
    const float* pos   = (const float*)d_in[1];
    const int*   batch = (const int*)d_in[2];
    const int*   idx   = (const int*)d_in[3];
    const float* W1 = (const float*)d_in[4];
    const float* b1 = (const float*)d_in[5];
    const float* W2 = (const float*)d_in[6];
    const float* b2 = (const float*)d_in[7];
    const float* W3 = (const float*)d_in[8];
    const float* b3 = (const float*)d_in[9];

    float* out = (float*)d_out;
    int writeAux = (out_size >= MCTR * 256 + MCTR * 3 + MCTR) ? 1 : 0;
    float* posout   = out + MCTR * 256;
    float* batchout = posout + MCTR * 3;

    prep_kernel<<<256, 256>>>(W1, W2, W3);
    knn_kernel<<<MCTR / 8, 256>>>(pos, batch, idx, posout, batchout, writeAux);

    cudaFuncSetAttribute(mlp_kernel, cudaFuncAttributeMaxDynamicSharedMemorySize, SMEM_TOTAL);
    mlp_kernel<<<MCTR / 4, 256, SMEM_TOTAL>>>(x, pos, idx, b1, b2, b3, out);
}